// round 4
// baseline (speedup 1.0000x reference)
#include <cuda_runtime.h>
#include <math.h>

#define BB 32
#define NN 1024
#define ITILE 128
#define JCH 256
#define NIT (NN/ITILE)        // 8 i-tiles
#define NJC (NN/JCH)          // 4 j-chunks
#define PWB (BB*NIT*NJC)      // 1024 pairwise blocks
#define TOTB (PWB+BB)         // + 32 stat blocks = 1056

__device__ float    g_part[BB*NJC*NN];   // D partials: [row][chunk][elem]
__device__ float    g_tt[BB], g_t5[BB], g_lw[BB], g_np[BB], g_sw[BB], g_tw[BB];
__device__ float    g_row[BB];
__device__ unsigned g_rc[BB];            // per-row arrival counters (zero-init)
__device__ unsigned g_cnt = 0;           // global arrival counter

__device__ __forceinline__ float tanh_ap(float x){
    float y; asm("tanh.approx.f32 %0, %1;" : "=f"(y) : "f"(x)); return y;
}

// block reductions for 128 threads (4 warps)
__device__ __forceinline__ float bsum128(float v, float* red, int t){
    #pragma unroll
    for (int o = 16; o; o >>= 1) v += __shfl_down_sync(0xffffffffu, v, o);
    if ((t & 31) == 0) red[t >> 5] = v;
    __syncthreads();
    if (t == 0) red[0] = red[0] + red[1] + red[2] + red[3];
    __syncthreads();
    v = red[0];
    __syncthreads();
    return v;
}
__device__ __forceinline__ float bmax128(float v, float* red, int t){
    #pragma unroll
    for (int o = 16; o; o >>= 1) v = fmaxf(v, __shfl_down_sync(0xffffffffu, v, o));
    if ((t & 31) == 0) red[t >> 5] = v;
    __syncthreads();
    if (t == 0) red[0] = fmaxf(fmaxf(red[0], red[1]), fmaxf(red[2], red[3]));
    __syncthreads();
    v = red[0];
    __syncthreads();
    return v;
}

// ---------------------------------------------------------------------------
// Single fused kernel (one wave, 1056 blocks x 128 threads):
//   blocks [0,1024): pairwise D_e partials (weight-free, register-only loop)
//   blocks [1024,1056): per-row bitonic sort -> thresholds, tie stats, listwise
//   33rd arriver per row: row combine; 32nd global arriver: final mean.
// ---------------------------------------------------------------------------
__global__ void __launch_bounds__(128, 8)
fused(const float* __restrict__ yp, const float* __restrict__ yt,
      float* __restrict__ out){
    __shared__ union {
        struct { float s[NN]; float red[4]; } row;
        struct { float2 ptj[JCH]; } pw;
    } sm;
    __shared__ float redc[4];
    __shared__ int   flagA, flagB;

    const int t = threadIdx.x;
    int row;

    if (blockIdx.x < PWB){
        // ================= pairwise tile (square form) =================
        row = blockIdx.x / (NIT*NJC);
        const int rest = blockIdx.x % (NIT*NJC);
        const int it = rest / NJC, jc = rest % NJC;
        const float* pr = yp + row*NN;
        const float* tr = yt + row*NN;
        const int j0 = jc*JCH;

        #pragma unroll
        for (int m = 0; m < 2; m++){
            int e = t + m*128;
            sm.pw.ptj[e] = make_float2(pr[j0+e]*0.5f, tr[j0+e]);
        }
        __syncthreads();

        const int   i   = it*ITILE + t;
        const float pih = pr[i]*0.5f;
        const float ti  = tr[i];
        float aG = 0.f, aL = 0.f;   // sum tanh over (ti>tj) and (ti<tj)

        const float4* pt4 = (const float4*)sm.pw.ptj;  // 2 j's per LDS.128
        #pragma unroll 4
        for (int j2 = 0; j2 < JCH/2; j2++){
            float4 c = pt4[j2];
            float th0 = tanh_ap(pih - c.x);
            aG += (ti > c.y) ? th0 : 0.f;
            aL += (ti < c.y) ? th0 : 0.f;
            float th1 = tanh_ap(pih - c.z);
            aG += (ti > c.w) ? th1 : 0.f;
            aL += (ti < c.w) ? th1 : 0.f;
        }
        // sig_ij = 0.5 - 0.5*sign(ti-tj)*tanh((pi-pj)/2);  D_e = aG - aL
        g_part[(row*NJC + jc)*NN + i] = aG - aL;
        __threadfence();
    } else {
        // ================= per-row sort + stats =================
        row = blockIdx.x - PWB;
        const float* pr = yp + row*NN;
        const float* tr = yt + row*NN;
        float* s   = sm.row.s;
        float* red = sm.row.red;

        #pragma unroll
        for (int m = 0; m < 8; m++) s[t + m*128] = tr[t + m*128];
        __syncthreads();

        for (int k = 2; k <= NN; k <<= 1){
            for (int j = k >> 1; j > 0; j >>= 1){
                #pragma unroll
                for (int m = 0; m < 8; m++){
                    int idx = t + m*128, p = idx ^ j;
                    if (p > idx){
                        float a = s[idx], b = s[p];
                        bool up = (idx & k) == 0;
                        if ((a > b) == up){ s[idx] = b; s[p] = a; }
                    }
                }
                __syncthreads();
            }
        }

        const float tt = s[972];     // tail mask == y >= interp-quantile(0.95)
        const float t5 = s[NN-5];    // top-5 mask
        const float mt = s[NN-1];    // row max y_true

        // tie-run stats: T2 = sum L(L-1), TW = sum L(L-1)*w(v)
        float tie2 = 0.f, tieW = 0.f;
        #pragma unroll
        for (int m = 0; m < 8; m++){
            int idx = t + m*128;
            float sv = s[idx];
            int d = 0, k2 = idx + 1;
            while (k2 < NN && s[k2] == sv){ ++d; ++k2; }
            if (d){
                float wv = ((sv >= tt) ? 10.f : 1.f) * ((sv >= t5) ? 2.f : 1.f);
                tie2 += 2.f * (float)d;
                tieW += 2.f * (float)d * wv;
            }
        }

        float pv[8], tvv[8];
        #pragma unroll
        for (int m = 0; m < 8; m++){ pv[m] = pr[t + m*128]; tvv[m] = tr[t + m*128]; }

        float mp = -3.4e38f;
        #pragma unroll
        for (int m = 0; m < 8; m++) mp = fmaxf(mp, pv[m]);
        mp = bmax128(mp, red, t);

        float spl = 0.f, stl = 0.f;
        #pragma unroll
        for (int m = 0; m < 8; m++){
            spl += __expf(pv[m]  - mp);
            stl += __expf(tvv[m] - mt);
        }
        const float sp = bsum128(spl, red, t);
        const float st = bsum128(stl, red, t);
        const float rsp = 1.0f/sp, rst = 1.0f/st;

        float numl = 0.f, denl = 0.f;
        #pragma unroll
        for (int m = 0; m < 8; m++){
            float tv = tvv[m];
            float wv = ((tv >= tt) ? 10.f : 1.f) * ((tv >= t5) ? 2.f : 1.f);
            float pp = __expf(pv[m] - mp) * rsp;
            float tp = __expf(tv    - mt) * rst;
            numl += tp * logf(pp + 1e-12f) * wv;
            denl += wv;
        }
        const float num = bsum128(numl, red, t);
        const float den = bsum128(denl, red, t);
        const float T2  = bsum128(tie2, red, t);
        const float TW  = bsum128(tieW, red, t);

        if (t == 0){
            g_tt[row] = tt;
            g_t5[row] = t5;
            g_lw[row] = -num / (den + 1e-12f);
            g_sw[row] = den;
            g_tw[row] = TW;
            float np = (float)NN*(float)(NN-1) - T2;
            if (np < 1.f) np = 1.f;
            g_np[row] = np;
        }
        __threadfence();
    }

    // ================= per-row arrival: 33rd block combines =================
    if (t == 0) flagA = (atomicAdd(&g_rc[row], 1u) == (NIT*NJC));
    __syncthreads();
    if (!flagA) return;

    __threadfence();
    if (t == 0) g_rc[row] = 0;   // reset for next graph replay

    const float tt = __ldcg(&g_tt[row]);
    const float t5 = __ldcg(&g_t5[row]);
    const float* tr = yt + row*NN;

    float acc = 0.f;
    #pragma unroll
    for (int m = 0; m < 8; m++){
        int e = t + m*128;
        float D = __ldcg(&g_part[(row*NJC+0)*NN + e])
                + __ldcg(&g_part[(row*NJC+1)*NN + e])
                + __ldcg(&g_part[(row*NJC+2)*NN + e])
                + __ldcg(&g_part[(row*NJC+3)*NN + e]);
        float tv = tr[e];
        float w  = ((tv >= tt) ? 10.f : 1.f) * ((tv >= t5) ? 2.f : 1.f);
        acc += w * D;
    }
    #pragma unroll
    for (int o = 16; o; o >>= 1) acc += __shfl_down_sync(0xffffffffu, acc, o);
    if ((t & 31) == 0) redc[t >> 5] = acc;
    __syncthreads();

    if (t == 0){
        float wD = redc[0] + redc[1] + redc[2] + redc[3];
        float Sw = __ldcg(&g_sw[row]);
        float TW = __ldcg(&g_tw[row]);
        float np = __ldcg(&g_np[row]);
        // pairwise = 2*sum_e w_e*S_e / np,  S_e = 0.5*cnt_e - 0.5*D_e
        //          = ((N-1)*Sw - TW - sum_e w_e*D_e) / np
        float pw = ((float)(NN-1)*Sw - TW - wD) / np;
        g_row[row] = __ldcg(&g_lw[row]) + pw;
        __threadfence();
        flagB = (atomicAdd(&g_cnt, 1u) == BB - 1);
    }
    __syncthreads();

    // ================= last row-combiner: final mean =================
    if (flagB){
        __threadfence();
        if (t < 32){
            float v = __ldcg(&g_row[t]);
            #pragma unroll
            for (int o = 16; o; o >>= 1) v += __shfl_down_sync(0xffffffffu, v, o);
            if (t == 0){
                out[0] = v * (1.0f/(float)BB);
                g_cnt = 0;   // reset for next graph replay
            }
        }
    }
}

// ---------------------------------------------------------------------------
extern "C" void kernel_launch(void* const* d_in, const int* in_sizes, int n_in,
                              void* d_out, int out_size){
    const float* yp = (const float*)d_in[0];   // y_pred [32,1024]
    const float* yt = (const float*)d_in[1];   // y_true [32,1024]
    fused<<<TOTB, 128>>>(yp, yt, (float*)d_out);
}

// round 7
// speedup vs baseline: 1.4353x; 1.4353x over previous
#include <cuda_runtime.h>
#include <math.h>

#define BB 32
#define NN 1024
#define NTILE 8                 // 8x8 tiles of 128
#define NTRI 36                 // upper-triangle tile count
#define PWB (BB*NTRI)           // 1152 pairwise blocks

__device__ float    g_tt[BB], g_t5[BB], g_lw[BB], g_np[BB], g_cst[BB];
__device__ double   g_pA[BB];            // zero-init; reset each replay
__device__ float    g_row[BB];
__device__ unsigned g_rc[BB];            // per-row arrival counters
__device__ unsigned g_cnt = 0;           // global arrival counter

__constant__ int c_bi[NTRI] = {0,0,0,0,0,0,0,0, 1,1,1,1,1,1,1, 2,2,2,2,2,2,
                               3,3,3,3,3, 4,4,4,4, 5,5,5, 6,6, 7};
__constant__ int c_bj[NTRI] = {0,1,2,3,4,5,6,7, 1,2,3,4,5,6,7, 2,3,4,5,6,7,
                               3,4,5,6,7, 4,5,6,7, 5,6,7, 6,7, 7};

__device__ __forceinline__ float tanh_ap(float x){
    float y; asm("tanh.approx.f32 %0, %1;" : "=f"(y) : "f"(x)); return y;
}

// block reductions for 1024 threads (32 warps)
__device__ __forceinline__ float bsum1024(float v, float* red, int t){
    #pragma unroll
    for (int o = 16; o; o >>= 1) v += __shfl_down_sync(0xffffffffu, v, o);
    if ((t & 31) == 0) red[t >> 5] = v;
    __syncthreads();
    if (t < 32){
        v = red[t];
        #pragma unroll
        for (int o = 16; o; o >>= 1) v += __shfl_down_sync(0xffffffffu, v, o);
        if (t == 0) red[0] = v;
    }
    __syncthreads();
    float r = red[0];
    __syncthreads();
    return r;
}
__device__ __forceinline__ float bmax1024(float v, float* red, int t){
    #pragma unroll
    for (int o = 16; o; o >>= 1) v = fmaxf(v, __shfl_down_sync(0xffffffffu, v, o));
    if ((t & 31) == 0) red[t >> 5] = v;
    __syncthreads();
    if (t < 32){
        v = red[t];
        #pragma unroll
        for (int o = 16; o; o >>= 1) v = fmaxf(v, __shfl_down_sync(0xffffffffu, v, o));
        if (t == 0) red[0] = v;
    }
    __syncthreads();
    float r = red[0];
    __syncthreads();
    return r;
}

// ---------------------------------------------------------------------------
// K1: per-row bitonic sort -> thresholds + tie stats + listwise CE
// ---------------------------------------------------------------------------
__global__ void __launch_bounds__(NN, 1)
k1(const float* __restrict__ yp, const float* __restrict__ yt){
    const int row = blockIdx.x, tid = threadIdx.x;
    __shared__ float s[NN];
    __shared__ float red[32];

    const float tv = yt[row*NN + tid];
    const float pv = yp[row*NN + tid];

    s[tid] = tv;
    __syncthreads();
    for (int k = 2; k <= NN; k <<= 1){
        for (int j = k >> 1; j > 0; j >>= 1){
            int ixj = tid ^ j;
            if (ixj > tid){
                float a = s[tid], b = s[ixj];
                bool up = (tid & k) == 0;
                if ((a > b) == up){ s[tid] = b; s[ixj] = a; }
            }
            __syncthreads();
        }
    }

    const float tt = s[972];      // tail mask == y >= interp-quantile(0.95)
    const float t5 = s[NN-5];     // top-5 mask
    const float mt = s[NN-1];     // row max of y_true

    // tie-run stats: T2 = sum L(L-1), TW = sum_i w_i * ties_i
    float tie2 = 0.f, tieW = 0.f;
    {
        const float sv = s[tid];
        int d = 0, k2 = tid + 1;
        while (k2 < NN && s[k2] == sv){ ++d; ++k2; }
        if (d){
            float wv = ((sv >= tt) ? 10.f : 1.f) * ((sv >= t5) ? 2.f : 1.f);
            tie2 = 2.f * (float)d;
            tieW = 2.f * (float)d * wv;
        }
    }

    const float w  = ((tv >= tt) ? 10.f : 1.f) * ((tv >= t5) ? 2.f : 1.f);
    const float mp = bmax1024(pv, red, tid);
    const float ep = __expf(pv - mp);
    const float et = __expf(tv - mt);
    const float sp = bsum1024(ep, red, tid);
    const float st = bsum1024(et, red, tid);

    const float pp  = ep / sp;
    const float tp  = et / st;
    const float num = bsum1024(tp * logf(pp + 1e-12f) * w, red, tid);
    const float den = bsum1024(w,    red, tid);
    const float T2  = bsum1024(tie2, red, tid);
    const float TW  = bsum1024(tieW, red, tid);

    if (tid == 0){
        g_tt[row]  = tt;
        g_t5[row]  = t5;
        g_lw[row]  = -num / (den + 1e-12f);
        g_cst[row] = (float)(NN-1) * den - TW;    // analytic 0.5-constant part
        float np = (float)NN * (float)(NN-1) - T2;
        if (np < 1.f) np = 1.f;
        g_np[row]  = np;
    }
}

// ---------------------------------------------------------------------------
// K2: pairwise A = sum_{i<j} (w_i+w_j)*sign(ti-tj)*tanh((pi-pj)/2)
//     (upper-triangle 128x128 tiles, 36 per row) + in-kernel combine.
//     row pairwise = (g_cst - A) / np ; final = mean(lw + pw).
// ---------------------------------------------------------------------------
__global__ void __launch_bounds__(128)
k2(const float* __restrict__ yp, const float* __restrict__ yt,
   float* __restrict__ out){
    __shared__ float4 sj[128];
    __shared__ float  red[4];
    __shared__ int    flagA, flagB;

    const int t   = threadIdx.x;
    const int row = blockIdx.x / NTRI;
    const int tl  = blockIdx.x % NTRI;
    const int bi  = c_bi[tl], bj = c_bj[tl];

    const float* pr = yp + row*NN;
    const float* tr = yt + row*NN;
    const float tt = g_tt[row], t5 = g_t5[row];

    {
        int jg = bj*128 + t;
        float tj = tr[jg];
        float wj = ((tj >= tt) ? 10.f : 1.f) * ((tj >= t5) ? 2.f : 1.f);
        sj[t] = make_float4(pr[jg]*0.5f, tj, wj, 0.f);
    }
    __syncthreads();

    const int   ig  = bi*128 + t;
    const float pih = pr[ig]*0.5f;
    const float ti  = tr[ig];
    const float wi  = ((ti >= tt) ? 10.f : 1.f) * ((ti >= t5) ? 2.f : 1.f);

    float aG = 0.f, aL = 0.f;
    if (bi == bj){
        for (int j = t + 1; j < 128; ++j){
            float4 c = sj[j];                       // broadcast LDS.128
            float th = tanh_ap(pih - c.x);
            float ws = wi + c.z;
            if (ti > c.y) aG = fmaf(ws, th, aG);    // predicated FFMA
            if (ti < c.y) aL = fmaf(ws, th, aL);
        }
    } else {
        #pragma unroll 4
        for (int j = 0; j < 128; ++j){
            float4 c = sj[j];
            float th = tanh_ap(pih - c.x);
            float ws = wi + c.z;
            if (ti > c.y) aG = fmaf(ws, th, aG);
            if (ti < c.y) aL = fmaf(ws, th, aL);
        }
    }
    float A = aG - aL;

    // block reduce (4 warps)
    #pragma unroll
    for (int o = 16; o; o >>= 1) A += __shfl_down_sync(0xffffffffu, A, o);
    if ((t & 31) == 0) red[t >> 5] = A;
    __syncthreads();

    if (t == 0){
        double Ab = (double)(red[0] + red[1] + red[2] + red[3]);
        atomicAdd(&g_pA[row], Ab);
        __threadfence();
        flagA = (atomicAdd(&g_rc[row], 1u) == NTRI - 1);
    }
    __syncthreads();
    if (!flagA) return;

    // ---- 36th tile of this row: combine row ----
    if (t == 0){
        __threadfence();
        double Atot = *((volatile double*)&g_pA[row]);
        g_pA[row] = 0.0;          // reset for next graph replay
        g_rc[row] = 0u;
        float pw = (g_cst[row] - (float)Atot) / g_np[row];
        g_row[row] = g_lw[row] + pw;
        __threadfence();
        flagB = (atomicAdd(&g_cnt, 1u) == BB - 1);
    }
    __syncthreads();

    // ---- last row-combiner: final mean ----
    if (flagB && t < 32){
        __threadfence();
        float v = ((volatile float*)g_row)[t];
        #pragma unroll
        for (int o = 16; o; o >>= 1) v += __shfl_down_sync(0xffffffffu, v, o);
        if (t == 0){
            out[0] = v * (1.0f/(float)BB);
            g_cnt = 0u;           // reset for next graph replay
        }
    }
}

// ---------------------------------------------------------------------------
extern "C" void kernel_launch(void* const* d_in, const int* in_sizes, int n_in,
                              void* d_out, int out_size){
    const float* yp = (const float*)d_in[0];   // y_pred [32,1024]
    const float* yt = (const float*)d_in[1];   // y_true [32,1024]
    k1<<<BB, NN>>>(yp, yt);
    k2<<<PWB, 128>>>(yp, yt, (float*)d_out);
}

// round 8
// speedup vs baseline: 1.6723x; 1.1651x over previous
#include <cuda_runtime.h>
#include <math.h>

#define BB 32
#define NN 1024
#define NTRI 36                 // upper-triangle tile count (8x8 tiles of 128)
#define PWB (BB*NTRI)           // 1152 pairwise blocks

__device__ float    g_tt[BB], g_t5[BB], g_lw[BB], g_np[BB], g_cst[BB];
__device__ double   g_pA[BB];            // zero-init; reset each replay
__device__ float    g_row[BB];
__device__ unsigned g_rc[BB];            // per-row arrival counters
__device__ unsigned g_cnt = 0;           // global arrival counter

__constant__ int c_bi[NTRI] = {0,0,0,0,0,0,0,0, 1,1,1,1,1,1,1, 2,2,2,2,2,2,
                               3,3,3,3,3, 4,4,4,4, 5,5,5, 6,6, 7};
__constant__ int c_bj[NTRI] = {0,1,2,3,4,5,6,7, 1,2,3,4,5,6,7, 2,3,4,5,6,7,
                               3,4,5,6,7, 4,5,6,7, 5,6,7, 6,7, 7};

__device__ __forceinline__ float tanh_ap(float x){
    float y; asm("tanh.approx.f32 %0, %1;" : "=f"(y) : "f"(x)); return y;
}

// bitonic compare-exchange via shuffle (j < 32)
__device__ __forceinline__ float cex_shfl(float v, int j, int k, int tid){
    float b = __shfl_xor_sync(0xffffffffu, v, j);
    bool up    = (tid & k) == 0;
    bool lower = (tid & j) == 0;
    return (lower == up) ? fminf(v, b) : fmaxf(v, b);
}

// block reductions for 1024 threads (32 warps)
__device__ __forceinline__ float bsum1024(float v, float* red, int t){
    #pragma unroll
    for (int o = 16; o; o >>= 1) v += __shfl_down_sync(0xffffffffu, v, o);
    if ((t & 31) == 0) red[t >> 5] = v;
    __syncthreads();
    if (t < 32){
        v = red[t];
        #pragma unroll
        for (int o = 16; o; o >>= 1) v += __shfl_down_sync(0xffffffffu, v, o);
        if (t == 0) red[0] = v;
    }
    __syncthreads();
    float r = red[0];
    __syncthreads();
    return r;
}
__device__ __forceinline__ float bmax1024(float v, float* red, int t){
    #pragma unroll
    for (int o = 16; o; o >>= 1) v = fmaxf(v, __shfl_down_sync(0xffffffffu, v, o));
    if ((t & 31) == 0) red[t >> 5] = v;
    __syncthreads();
    if (t < 32){
        v = red[t];
        #pragma unroll
        for (int o = 16; o; o >>= 1) v = fmaxf(v, __shfl_down_sync(0xffffffffu, v, o));
        if (t == 0) red[0] = v;
    }
    __syncthreads();
    float r = red[0];
    __syncthreads();
    return r;
}

// ---------------------------------------------------------------------------
// K1: per-row hybrid bitonic sort (shuffle for j<32, double-buffered smem for
//     j>=32: 15 barriers total) -> thresholds + tie stats + listwise CE
// ---------------------------------------------------------------------------
__global__ void __launch_bounds__(NN, 1)
k1(const float* __restrict__ yp, const float* __restrict__ yt){
    const int row = blockIdx.x, tid = threadIdx.x;
    __shared__ float buf[2][NN];
    __shared__ float red[32];

    const float tv = yt[row*NN + tid];
    const float pv = yp[row*NN + tid];

    float v = tv;
    // k <= 32: all-shuffle stages
    #pragma unroll
    for (int k = 2; k <= 32; k <<= 1)
        #pragma unroll
        for (int j = k >> 1; j > 0; j >>= 1)
            v = cex_shfl(v, j, k, tid);

    // k >= 64: smem stages for j>=32 (1 bar each, alternating buffers), then shuffles
    int p = 0;
    #pragma unroll
    for (int k = 64; k <= NN; k <<= 1){
        for (int j = k >> 1; j >= 32; j >>= 1){
            buf[p][tid] = v;
            __syncthreads();
            float b = buf[p][tid ^ j];
            bool up    = (tid & k) == 0;
            bool lower = (tid & j) == 0;
            v = (lower == up) ? fminf(v, b) : fmaxf(v, b);
            p ^= 1;
        }
        #pragma unroll
        for (int j = 16; j > 0; j >>= 1)
            v = cex_shfl(v, j, k, tid);
    }
    buf[0][tid] = v;
    __syncthreads();
    const float* s = buf[0];

    const float tt = s[972];      // tail mask == y >= interp-quantile(0.95)
    const float t5 = s[NN-5];     // top-5 mask
    const float mt = s[NN-1];     // row max of y_true

    // tie-run stats: T2 = sum L(L-1), TW = sum L(L-1)*w(v)
    float tie2 = 0.f, tieW = 0.f;
    {
        const float sv = s[tid];
        int d = 0, k2 = tid + 1;
        while (k2 < NN && s[k2] == sv){ ++d; ++k2; }
        if (d){
            float wv = ((sv >= tt) ? 10.f : 1.f) * ((sv >= t5) ? 2.f : 1.f);
            tie2 = 2.f * (float)d;
            tieW = 2.f * (float)d * wv;
        }
    }

    const float w  = ((tv >= tt) ? 10.f : 1.f) * ((tv >= t5) ? 2.f : 1.f);
    const float mp = bmax1024(pv, red, tid);
    const float ep = __expf(pv - mp);
    const float et = __expf(tv - mt);
    const float sp = bsum1024(ep, red, tid);
    const float st = bsum1024(et, red, tid);

    const float pp  = ep / sp;
    const float tp  = et / st;
    const float num = bsum1024(tp * logf(pp + 1e-12f) * w, red, tid);
    const float den = bsum1024(w,    red, tid);
    const float T2  = bsum1024(tie2, red, tid);
    const float TW  = bsum1024(tieW, red, tid);

    if (tid == 0){
        g_tt[row]  = tt;
        g_t5[row]  = t5;
        g_lw[row]  = -num / (den + 1e-12f);
        g_cst[row] = (float)(NN-1) * den - TW;    // analytic 0.5-constant part
        float np = (float)NN * (float)(NN-1) - T2;
        if (np < 1.f) np = 1.f;
        g_np[row]  = np;
    }
}

// ---------------------------------------------------------------------------
// K2: pairwise A = sum_{i<j} (w_i+w_j)*sign(ti-tj)*tanh((pi-pj)/2)
//     8-wide prefetch + even/odd accumulators; in-kernel combine.
// ---------------------------------------------------------------------------
#define PROC(c, G, L)                                   \
    {                                                   \
        float th = tanh_ap(pih - (c).x);                \
        float ws = wi + (c).z;                          \
        if (ti > (c).y) G = fmaf(ws, th, G);            \
        if (ti < (c).y) L = fmaf(ws, th, L);            \
    }

__global__ void __launch_bounds__(128)
k2(const float* __restrict__ yp, const float* __restrict__ yt,
   float* __restrict__ out){
    __shared__ float4 sj[128];
    __shared__ float  red[4];
    __shared__ int    flagA, flagB;

    const int t   = threadIdx.x;
    const int row = blockIdx.x / NTRI;
    const int tl  = blockIdx.x % NTRI;
    const int bi  = c_bi[tl], bj = c_bj[tl];

    const float* pr = yp + row*NN;
    const float* tr = yt + row*NN;
    const float tt = g_tt[row], t5 = g_t5[row];

    {
        int jg = bj*128 + t;
        float tj = tr[jg];
        float wj = ((tj >= tt) ? 10.f : 1.f) * ((tj >= t5) ? 2.f : 1.f);
        sj[t] = make_float4(pr[jg]*0.5f, tj, wj, 0.f);
    }
    __syncthreads();

    const int   ig  = bi*128 + t;
    const float pih = pr[ig]*0.5f;
    const float ti  = tr[ig];
    const float wi  = ((ti >= tt) ? 10.f : 1.f) * ((ti >= t5) ? 2.f : 1.f);

    float aG = 0.f, aL = 0.f, bG = 0.f, bL = 0.f;
    if (bi == bj){
        for (int j = t + 1; j < 128; ++j){
            float4 c = sj[j];
            PROC(c, aG, aL);
        }
    } else {
        for (int jb = 0; jb < 128; jb += 8){
            float4 c0 = sj[jb+0], c1 = sj[jb+1], c2 = sj[jb+2], c3 = sj[jb+3];
            float4 c4 = sj[jb+4], c5 = sj[jb+5], c6 = sj[jb+6], c7 = sj[jb+7];
            PROC(c0, aG, aL); PROC(c1, bG, bL);
            PROC(c2, aG, aL); PROC(c3, bG, bL);
            PROC(c4, aG, aL); PROC(c5, bG, bL);
            PROC(c6, aG, aL); PROC(c7, bG, bL);
        }
    }
    float A = (aG + bG) - (aL + bL);

    // block reduce (4 warps)
    #pragma unroll
    for (int o = 16; o; o >>= 1) A += __shfl_down_sync(0xffffffffu, A, o);
    if ((t & 31) == 0) red[t >> 5] = A;
    __syncthreads();

    if (t == 0){
        double Ab = (double)(red[0] + red[1] + red[2] + red[3]);
        atomicAdd(&g_pA[row], Ab);
        __threadfence();
        flagA = (atomicAdd(&g_rc[row], 1u) == NTRI - 1);
    }
    __syncthreads();
    if (!flagA) return;

    // ---- 36th tile of this row: combine row ----
    if (t == 0){
        __threadfence();
        double Atot = *((volatile double*)&g_pA[row]);
        g_pA[row] = 0.0;          // reset for next graph replay
        g_rc[row] = 0u;
        float pw = (g_cst[row] - (float)Atot) / g_np[row];
        g_row[row] = g_lw[row] + pw;
        __threadfence();
        flagB = (atomicAdd(&g_cnt, 1u) == BB - 1);
    }
    __syncthreads();

    // ---- last row-combiner: final mean ----
    if (flagB && t < 32){
        __threadfence();
        float v = ((volatile float*)g_row)[t];
        #pragma unroll
        for (int o = 16; o; o >>= 1) v += __shfl_down_sync(0xffffffffu, v, o);
        if (t == 0){
            out[0] = v * (1.0f/(float)BB);
            g_cnt = 0u;           // reset for next graph replay
        }
    }
}

// ---------------------------------------------------------------------------
extern "C" void kernel_launch(void* const* d_in, const int* in_sizes, int n_in,
                              void* d_out, int out_size){
    const float* yp = (const float*)d_in[0];   // y_pred [32,1024]
    const float* yt = (const float*)d_in[1];   // y_true [32,1024]
    k1<<<BB, NN>>>(yp, yt);
    k2<<<PWB, 128>>>(yp, yt, (float*)d_out);
}